// round 12
// baseline (speedup 1.0000x reference)
#include <cuda_runtime.h>
#include <math.h>
#include <float.h>

#define NB      64
#define TOKENS  784
#define DIM     768
#define FH      28
#define IMG     448
#define TOPK    8
#define PATCH   16

__device__ float g_dist[NB * TOKENS];
__device__ int   g_box[NB][4];   // x0, x1, y0, y1

// ---------------------------------------------------------------------------
// Kernel 1: score = dot(g, l) / ||l||  (g-norm positive per-batch constant
// -> same ordering as cosine). grid (64,25) x 256, 4 rows per warp: 24
// independent LDG.128 in flight per warp -> denser load issue relative to
// the fixed shuffle-reduction tail.
// ---------------------------------------------------------------------------
__global__ void __launch_bounds__(256) sim_kernel(const float* __restrict__ x) {
    int b = blockIdx.x;
    int s = blockIdx.y;                       // 0..24 -> 32 rows per block
    const float* xb = x + (size_t)b * 785 * DIM;

    __shared__ float4 g_sh[DIM / 4];          // CLS token, 3 KB
    int tid = threadIdx.x;
    if (tid < DIM / 4) g_sh[tid] = ((const float4*)xb)[tid];
    __syncthreads();

    int warp = tid >> 5, lane = tid & 31;
    int r = s * 32 + warp * 4;                // this warp's 4 rows
    if (r >= TOKENS) return;
    bool full = (r + 4 <= TOKENS);

    const float4* l0 = (const float4*)(xb + (size_t)(1 + r) * DIM);
    const float4* l1 = (const float4*)(xb + (size_t)(2 + r) * DIM);
    const float4* l2 = (const float4*)(xb + (size_t)(3 + r) * DIM);
    const float4* l3 = (const float4*)(xb + (size_t)(4 + r) * DIM);
    float d0 = 0.f, n0 = 0.f, d1 = 0.f, n1 = 0.f;
    float d2 = 0.f, n2 = 0.f, d3 = 0.f, n3 = 0.f;

    if (full) {
#pragma unroll
        for (int j = 0; j < 6; ++j) {
            int o = lane + 32 * j;
            float4 a = l0[o], c = l1[o], e = l2[o], f = l3[o];
            float4 g = g_sh[o];
            d0 += a.x * g.x + a.y * g.y + a.z * g.z + a.w * g.w;
            n0 += a.x * a.x + a.y * a.y + a.z * a.z + a.w * a.w;
            d1 += c.x * g.x + c.y * g.y + c.z * g.z + c.w * g.w;
            n1 += c.x * c.x + c.y * c.y + c.z * c.z + c.w * c.w;
            d2 += e.x * g.x + e.y * g.y + e.z * g.z + e.w * g.w;
            n2 += e.x * e.x + e.y * e.y + e.z * e.z + e.w * e.w;
            d3 += f.x * g.x + f.y * g.y + f.z * g.z + f.w * g.w;
            n3 += f.x * f.x + f.y * f.y + f.z * f.z + f.w * f.w;
        }
    } else {
        // tail rows (only in the last y-block): guard per row
#pragma unroll
        for (int j = 0; j < 6; ++j) {
            int o = lane + 32 * j;
            float4 g = g_sh[o];
            float4 a = l0[o];
            d0 += a.x * g.x + a.y * g.y + a.z * g.z + a.w * g.w;
            n0 += a.x * a.x + a.y * a.y + a.z * a.z + a.w * a.w;
            if (r + 1 < TOKENS) {
                float4 c = l1[o];
                d1 += c.x * g.x + c.y * g.y + c.z * g.z + c.w * g.w;
                n1 += c.x * c.x + c.y * c.y + c.z * c.z + c.w * c.w;
            }
            if (r + 2 < TOKENS) {
                float4 e = l2[o];
                d2 += e.x * g.x + e.y * g.y + e.z * g.z + e.w * g.w;
                n2 += e.x * e.x + e.y * e.y + e.z * e.z + e.w * e.w;
            }
            if (r + 3 < TOKENS) {
                float4 f = l3[o];
                d3 += f.x * g.x + f.y * g.y + f.z * g.z + f.w * g.w;
                n3 += f.x * f.x + f.y * f.y + f.z * f.z + f.w * f.w;
            }
        }
    }
#pragma unroll
    for (int off = 16; off; off >>= 1) {
        d0 += __shfl_xor_sync(0xffffffffu, d0, off);
        n0 += __shfl_xor_sync(0xffffffffu, n0, off);
        d1 += __shfl_xor_sync(0xffffffffu, d1, off);
        n1 += __shfl_xor_sync(0xffffffffu, n1, off);
        d2 += __shfl_xor_sync(0xffffffffu, d2, off);
        n2 += __shfl_xor_sync(0xffffffffu, n2, off);
        d3 += __shfl_xor_sync(0xffffffffu, d3, off);
        n3 += __shfl_xor_sync(0xffffffffu, n3, off);
    }
    if (lane == 0) {
        float* dst = g_dist + b * TOKENS + r;
        dst[0] = d0 / fmaxf(sqrtf(n0), 1e-8f);
        if (r + 1 < TOKENS) dst[1] = d1 / fmaxf(sqrtf(n1), 1e-8f);
        if (r + 2 < TOKENS) dst[2] = d2 / fmaxf(sqrtf(n2), 1e-8f);
        if (r + 3 < TOKENS) dst[3] = d3 / fmaxf(sqrtf(n3), 1e-8f);
    }
}

// ---------------------------------------------------------------------------
// Kernel 2: top-8 argmax rounds (stable ties -> lower index), bounding box.
// ---------------------------------------------------------------------------
__global__ void topk_kernel() {
    int b = blockIdx.x;
    int lane = threadIdx.x;                   // 32 threads
    __shared__ float dist[TOKENS];
    for (int i = lane; i < TOKENS; i += 32) dist[i] = g_dist[b * TOKENS + i];
    __syncwarp();

    int minx = FH, maxx = -1, miny = FH, maxy = -1;
#pragma unroll 1
    for (int k = 0; k < TOPK; ++k) {
        float best = -FLT_MAX; int bi = TOKENS;
        for (int i = lane; i < TOKENS; i += 32) {
            float v = dist[i];
            if (v > best) { best = v; bi = i; }   // strict > keeps lowest idx
        }
#pragma unroll
        for (int off = 16; off; off >>= 1) {
            float ov = __shfl_xor_sync(0xffffffffu, best, off);
            int   oi = __shfl_xor_sync(0xffffffffu, bi,   off);
            if (ov > best || (ov == best && oi < bi)) { best = ov; bi = oi; }
        }
        if (lane == 0) dist[bi] = -FLT_MAX;
        __syncwarp();
        int ix = bi / FH, iy = bi % FH;
        minx = min(minx, ix); maxx = max(maxx, ix);
        miny = min(miny, iy); maxy = max(maxy, iy);
    }
    if (lane == 0) {
        int x_i = minx * PATCH, x_f = maxx * PATCH;
        int y_i = miny * PATCH, y_f = maxy * PATCH;
        g_box[b][0] = max(x_i, 0);
        g_box[b][1] = min(max(x_f, x_i + PATCH), IMG);
        g_box[b][2] = max(y_i, 0);
        g_box[b][3] = min(max(y_f, y_i + PATCH), IMG);
    }
}

// ---------------------------------------------------------------------------
// Kernel 3: separable bilinear crop-resize, warp-autonomous, ROWG=28.
// Block = (b, c, 28 output rows), 448 threads / 14 warps; each warp owns a
// 32-column window for both phases (only __syncwarp needed). 28 output rows
// touch at most 29 source rows (slope <= 1). smem 50.8 KB; occupancy still
// thread-limited at 4 blocks/SM, but 43% fewer blocks than ROWG=16 and
// boundary-row re-read overhead drops to 3.6%.
// ---------------------------------------------------------------------------
#define ROWG 28
__global__ void __launch_bounds__(448) resize_kernel(
        const float* __restrict__ images, float* __restrict__ out) {
    int blk = blockIdx.x;
    int g  = blk % (IMG / ROWG);
    int t  = blk / (IMG / ROWG);
    int c  = t % 3;
    int b  = t / 3;
    int ty0 = g * ROWG;
    int tid  = threadIdx.x;
    int warp = tid >> 5;                      // 0..13
    int lane = tid & 31;
    int col  = (warp << 5) + lane;            // this thread's output column

    __shared__ __align__(16) float hrow[(ROWG + 1) * IMG];  // 29*448*4 = 50.8 KB

    int4 bx = *(const int4*)&g_box[b][0];
    int x0 = bx.x, x1 = bx.y, y0 = bx.z, y1 = bx.w;

    const float scale = 1.0f / (float)(IMG - 1);
    float hstep = ((float)(x1 - x0) - 1.0f) * scale;   // <= 1
    float wstep = ((float)(y1 - y0) - 1.0f) * scale;

    int rlo = (int)floorf((float)x0 + (float)ty0 * hstep);
    int rhi = min((int)floorf((float)x0 + (float)(ty0 + ROWG - 1) * hstep) + 1,
                  x1 - 1);
    int nrows = rhi - rlo + 1;                // <= 29

    const float* src = images + (size_t)(b * 3 + c) * IMG * IMG;

    // Phase A: horizontal lerp from global, one column per thread
    {
        float sx  = (float)y0 + (float)col * wstep;
        int   xlo = (int)floorf(sx);
        int   xhi = min(xlo + 1, y1 - 1);
        float wx  = sx - (float)xlo;
        const float* p = src + (size_t)rlo * IMG;
#pragma unroll
        for (int rr = 0; rr < ROWG + 1; ++rr) {
            if (rr < nrows) {
                float a  = __ldg(p + (size_t)rr * IMG + xlo);
                float bv = __ldg(p + (size_t)rr * IMG + xhi);
                hrow[rr * IMG + col] = a + wx * (bv - a);
            }
        }
    }
    __syncwarp();

    // Phase B: vertical lerp over this warp's 32-column window (8 quads/row).
    // 28 rows * 8 quads = 224 quads / 32 lanes = 7 iterations.
    float* obase = out + (size_t)(b * 3 + c) * IMG * IMG;
#pragma unroll
    for (int it = 0; it < ROWG / 4; ++it) {
        int j   = (it << 5) + lane;
        int tyl = j >> 3;                     // 0..27
        int q   = j & 7;
        int txq = (warp << 3) + q;
        int ty  = ty0 + tyl;

        float sy  = (float)x0 + (float)ty * hstep;
        int   ylo = (int)floorf(sy);
        int   yhi = min(ylo + 1, x1 - 1);
        float wy  = sy - (float)ylo;

        float4 h0 = ((const float4*)(hrow + (ylo - rlo) * IMG))[txq];
        float4 h1 = ((const float4*)(hrow + (yhi - rlo) * IMG))[txq];
        float4 res;
        res.x = h0.x + wy * (h1.x - h0.x);
        res.y = h0.y + wy * (h1.y - h0.y);
        res.z = h0.z + wy * (h1.z - h0.z);
        res.w = h0.w + wy * (h1.w - h0.w);
        __stcs((float4*)(obase + (size_t)ty * IMG) + txq, res);
    }
}

// ---------------------------------------------------------------------------
extern "C" void kernel_launch(void* const* d_in, const int* in_sizes, int n_in,
                              void* d_out, int out_size) {
    const float* x      = (const float*)d_in[0];
    const float* images = (const float*)d_in[1];
    const int X_ELEMS   = NB * 785 * DIM;
    if (n_in >= 2 && in_sizes[0] != X_ELEMS) {
        x      = (const float*)d_in[1];
        images = (const float*)d_in[0];
    }
    float* out = (float*)d_out;

    dim3 g1(NB, 25);
    sim_kernel<<<g1, 256>>>(x);
    topk_kernel<<<NB, 32>>>();
    resize_kernel<<<NB * 3 * (IMG / ROWG), 448>>>(images, out);
}

// round 13
// speedup vs baseline: 1.0429x; 1.0429x over previous
#include <cuda_runtime.h>
#include <math.h>
#include <float.h>

#define NB      64
#define TOKENS  784
#define DIM     768
#define FH      28
#define IMG     448
#define TOPK    8
#define PATCH   16

__device__ float    g_dist[NB * TOKENS];
__device__ int      g_box[NB][4];   // x0, x1, y0, y1
__device__ unsigned g_cnt[NB];      // zero-initialized; reset by consumer

// ---------------------------------------------------------------------------
// Kernel 1: score = dot(g, l) / ||l||  (g-norm positive per-batch constant
// -> same ordering as cosine). grid (64,49) x 256, 2 rows per warp (R9/R10
// sweet spot: 3136 blocks, 12 in-flight LDG.128 per warp).
// FUSED topk tail: the last sim block of each batch (atomic counter) runs
// the top-8 argmax + bounding box with warp 0 — removes the topk launch.
// ---------------------------------------------------------------------------
__global__ void __launch_bounds__(256) sim_kernel(const float* __restrict__ x) {
    int b = blockIdx.x;
    int s = blockIdx.y;                       // 0..48 -> 16 rows per block
    const float* xb = x + (size_t)b * 785 * DIM;

    __shared__ float4 g_sh[DIM / 4];          // CLS token, 3 KB
    __shared__ bool   is_last;
    int tid = threadIdx.x;
    if (tid < DIM / 4) g_sh[tid] = ((const float4*)xb)[tid];
    __syncthreads();

    int warp = tid >> 5, lane = tid & 31;
    int r = s * 16 + warp * 2;                // this warp's row pair
    const float4* l0 = (const float4*)(xb + (size_t)(1 + r) * DIM);
    const float4* l1 = (const float4*)(xb + (size_t)(2 + r) * DIM);
    float d0 = 0.f, n0 = 0.f, d1 = 0.f, n1 = 0.f;
#pragma unroll
    for (int j = 0; j < 6; ++j) {
        float4 a = l0[lane + 32 * j];
        float4 c = l1[lane + 32 * j];
        float4 g = g_sh[lane + 32 * j];
        d0 += a.x * g.x + a.y * g.y + a.z * g.z + a.w * g.w;
        n0 += a.x * a.x + a.y * a.y + a.z * a.z + a.w * a.w;
        d1 += c.x * g.x + c.y * g.y + c.z * g.z + c.w * g.w;
        n1 += c.x * c.x + c.y * c.y + c.z * c.z + c.w * c.w;
    }
#pragma unroll
    for (int off = 16; off; off >>= 1) {
        d0 += __shfl_xor_sync(0xffffffffu, d0, off);
        n0 += __shfl_xor_sync(0xffffffffu, n0, off);
        d1 += __shfl_xor_sync(0xffffffffu, d1, off);
        n1 += __shfl_xor_sync(0xffffffffu, n1, off);
    }
    if (lane == 0) {
        g_dist[b * TOKENS + r]     = d0 / fmaxf(sqrtf(n0), 1e-8f);
        g_dist[b * TOKENS + r + 1] = d1 / fmaxf(sqrtf(n1), 1e-8f);
    }

    // ---- last-block-done: run topk for this batch ----
    __syncthreads();
    if (tid == 0) {
        __threadfence();
        is_last = (atomicAdd(&g_cnt[b], 1u) == 48u);
    }
    __syncthreads();
    if (!is_last || warp != 0) return;

    // warp 0 of the last block: top-8 (stable: ties -> lower index) + bbox
    __shared__ float dist[TOKENS];
    for (int i = lane; i < TOKENS; i += 32) dist[i] = g_dist[b * TOKENS + i];
    __syncwarp();

    int minx = FH, maxx = -1, miny = FH, maxy = -1;
#pragma unroll 1
    for (int k = 0; k < TOPK; ++k) {
        float best = -FLT_MAX; int bi = TOKENS;
        for (int i = lane; i < TOKENS; i += 32) {
            float v = dist[i];
            if (v > best) { best = v; bi = i; }   // strict > keeps lowest idx
        }
#pragma unroll
        for (int off = 16; off; off >>= 1) {
            float ov = __shfl_xor_sync(0xffffffffu, best, off);
            int   oi = __shfl_xor_sync(0xffffffffu, bi,   off);
            if (ov > best || (ov == best && oi < bi)) { best = ov; bi = oi; }
        }
        if (lane == 0) dist[bi] = -FLT_MAX;
        __syncwarp();
        int ix = bi / FH, iy = bi % FH;
        minx = min(minx, ix); maxx = max(maxx, ix);
        miny = min(miny, iy); maxy = max(maxy, iy);
    }
    if (lane == 0) {
        int x_i = minx * PATCH, x_f = maxx * PATCH;
        int y_i = miny * PATCH, y_f = maxy * PATCH;
        g_box[b][0] = max(x_i, 0);
        g_box[b][1] = min(max(x_f, x_i + PATCH), IMG);
        g_box[b][2] = max(y_i, 0);
        g_box[b][3] = min(max(y_f, y_i + PATCH), IMG);
        g_cnt[b] = 0u;                        // reset for next graph replay
    }
}

// ---------------------------------------------------------------------------
// Kernel 3: separable bilinear crop-resize, warp-autonomous, ROWG=16 (R10).
// Block = (b, c, 16 output rows), 448 threads / 14 warps; each warp owns a
// 32-column window for BOTH phases -> only __syncwarp needed.
// Phase A: horizontal lerp from GLOBAL into hrow (17 rows x 2 independent
// near-unit-stride LDGs per thread). Phase B: vertical lerp, float4 LDS +
// __stcs STG.128 (output written once, never re-read).
// ---------------------------------------------------------------------------
#define ROWG 16
__global__ void __launch_bounds__(448) resize_kernel(
        const float* __restrict__ images, float* __restrict__ out) {
    int blk = blockIdx.x;
    int g  = blk % (IMG / ROWG);
    int t  = blk / (IMG / ROWG);
    int c  = t % 3;
    int b  = t / 3;
    int ty0 = g * ROWG;
    int tid  = threadIdx.x;
    int warp = tid >> 5;                      // 0..13
    int lane = tid & 31;
    int col  = (warp << 5) + lane;            // this thread's output column

    __shared__ __align__(16) float hrow[(ROWG + 1) * IMG];  // 29.8 KB

    int4 bx = *(const int4*)&g_box[b][0];
    int x0 = bx.x, x1 = bx.y, y0 = bx.z, y1 = bx.w;

    const float scale = 1.0f / (float)(IMG - 1);
    float hstep = ((float)(x1 - x0) - 1.0f) * scale;   // <= 1
    float wstep = ((float)(y1 - y0) - 1.0f) * scale;

    int rlo = (int)floorf((float)x0 + (float)ty0 * hstep);
    int rhi = min((int)floorf((float)x0 + (float)(ty0 + ROWG - 1) * hstep) + 1,
                  x1 - 1);
    int nrows = rhi - rlo + 1;                // <= 17

    const float* src = images + (size_t)(b * 3 + c) * IMG * IMG;

    // Phase A: horizontal lerp from global, one column per thread
    {
        float sx  = (float)y0 + (float)col * wstep;
        int   xlo = (int)floorf(sx);
        int   xhi = min(xlo + 1, y1 - 1);
        float wx  = sx - (float)xlo;
        const float* p = src + (size_t)rlo * IMG;
#pragma unroll
        for (int rr = 0; rr < ROWG + 1; ++rr) {
            if (rr < nrows) {
                float a  = __ldg(p + (size_t)rr * IMG + xlo);
                float bv = __ldg(p + (size_t)rr * IMG + xhi);
                hrow[rr * IMG + col] = a + wx * (bv - a);
            }
        }
    }
    __syncwarp();

    // Phase B: vertical lerp over this warp's 32-column window
    float* obase = out + (size_t)(b * 3 + c) * IMG * IMG;
#pragma unroll
    for (int it = 0; it < ROWG / 4; ++it) {
        int j   = (it << 5) + lane;
        int tyl = j >> 3;
        int q   = j & 7;
        int txq = (warp << 3) + q;
        int ty  = ty0 + tyl;

        float sy  = (float)x0 + (float)ty * hstep;
        int   ylo = (int)floorf(sy);
        int   yhi = min(ylo + 1, x1 - 1);
        float wy  = sy - (float)ylo;

        float4 h0 = ((const float4*)(hrow + (ylo - rlo) * IMG))[txq];
        float4 h1 = ((const float4*)(hrow + (yhi - rlo) * IMG))[txq];
        float4 res;
        res.x = h0.x + wy * (h1.x - h0.x);
        res.y = h0.y + wy * (h1.y - h0.y);
        res.z = h0.z + wy * (h1.z - h0.z);
        res.w = h0.w + wy * (h1.w - h0.w);
        __stcs((float4*)(obase + (size_t)ty * IMG) + txq, res);
    }
}

// ---------------------------------------------------------------------------
extern "C" void kernel_launch(void* const* d_in, const int* in_sizes, int n_in,
                              void* d_out, int out_size) {
    const float* x      = (const float*)d_in[0];
    const float* images = (const float*)d_in[1];
    const int X_ELEMS   = NB * 785 * DIM;
    if (n_in >= 2 && in_sizes[0] != X_ELEMS) {
        x      = (const float*)d_in[1];
        images = (const float*)d_in[0];
    }
    float* out = (float*)d_out;

    dim3 g1(NB, 49);
    sim_kernel<<<g1, 256>>>(x);
    resize_kernel<<<NB * 3 * (IMG / ROWG), 448>>>(images, out);
}